// round 2
// baseline (speedup 1.0000x reference)
#include <cuda_runtime.h>

// Kobayashi dendrite growth, single timestep, fused.
// B=4, H=W=2048, periodic boundaries, fp32.
// Output: [phi_new (B*H*W) | tempr_new (B*H*W)] concatenated.

#define Wd 2048
#define Hd 2048
#define BATCH 4
#define TX 32
#define TY 16

// Physical constants
#define EPSB    0.01f
#define EB_D    2.0e-4f       // EPSB * DELTA
#define EDCOEF  (-1.2e-3f)    // -EPSB * ANISO * DELTA
#define C6T0    0.3623577545f // cos(6*0.2)
#define S6T0    0.9320390860f // sin(6*0.2)
#define APIX    0.2864788976f // ALPHA/pi
#define GAMMA_  10.0f
#define TEQ_    1.0f
#define DTTAU   (1.0f/3.0f)   // DT/TAU
#define DTc     1.0e-4f
#define KAPPA_  1.8f
#define INVDX2  1111.111111f  // 1/dx^2  (dx=dy=0.03)
#define C_CROSS 277.7777778f  // 1/(2dx) * 1/(2dy)

__global__ __launch_bounds__(TX*TY, 2)
void dendrite_kernel(const float* __restrict__ phi,
                     const float* __restrict__ tempr,
                     float* __restrict__ out_phi,
                     float* __restrict__ out_tmp)
{
    // phi needs +-2 halo, tempr/prod need +-1 halo
    __shared__ float s_phi[TY+4][TX+4];   // 20 x 36
    __shared__ float s_tmp[TY+2][TX+2];   // 18 x 34
    __shared__ float s_p1 [TY+2][TX+2];
    __shared__ float s_p2 [TY+2][TX+2];
    __shared__ float s_e2 [TY+2][TX+2];

    const int tx  = threadIdx.x;
    const int ty  = threadIdx.y;
    const int tid = ty * TX + tx;
    const int x0  = blockIdx.x * TX;
    const int y0  = blockIdx.y * TY;
    const int base = (int)blockIdx.z * (Hd * Wd);

    // --- load phi region [y0-2, y0+TY+2) x [x0-2, x0+TX+2), periodic wrap
    #pragma unroll
    for (int i = tid; i < (TY+4)*(TX+4); i += TX*TY) {
        int ly = i / (TX+4), lx = i % (TX+4);
        int gy = (y0 + ly - 2) & (Hd - 1);
        int gx = (x0 + lx - 2) & (Wd - 1);
        s_phi[ly][lx] = __ldg(&phi[base + gy * Wd + gx]);
    }
    // --- load tempr region [y0-1, y0+TY+1) x [x0-1, x0+TX+1)
    #pragma unroll
    for (int i = tid; i < (TY+2)*(TX+2); i += TX*TY) {
        int ly = i / (TX+2), lx = i % (TX+2);
        int gy = (y0 + ly - 1) & (Hd - 1);
        int gx = (x0 + lx - 1) & (Wd - 1);
        s_tmp[ly][lx] = __ldg(&tempr[base + gy * Wd + gx]);
    }
    __syncthreads();

    // --- stage 1: prod_mat1, prod_mat2, eps^2 on the (TY+2)x(TX+2) halo region
    #pragma unroll
    for (int i = tid; i < (TY+2)*(TX+2); i += TX*TY) {
        int ly = i / (TX+2), lx = i % (TX+2);
        // raw central differences (scale 1/(2dx) folded into C_CROSS later;
        // direction for theta is unaffected by the positive scale)
        float gxr = s_phi[ly+1][lx+2] - s_phi[ly+1][lx];
        float gyr = s_phi[ly+2][lx+1] - s_phi[ly][lx+1];
        float r2  = fmaf(gxr, gxr, gyr * gyr);
        float inv = rsqrtf(r2);
        float c = gxr * inv;
        float s = gyr * inv;
        if (r2 == 0.0f) { c = 1.0f; s = 0.0f; }   // atan2(0,0)=0 convention
        // cos(6t) = T6(c), sin(6t) = s*U5(c)
        float x2 = c * c;
        float c6 = fmaf(fmaf(fmaf(x2, 32.0f, -48.0f), x2, 18.0f), x2, -1.0f);
        float s6 = (s * c) * fmaf(fmaf(x2, 32.0f, -32.0f), x2, 6.0f);
        // rotate by -6*theta0
        float cosA = fmaf(c6, C6T0, s6 * S6T0);
        float sinA = fmaf(s6, C6T0, -c6 * S6T0);
        float eps  = fmaf(cosA, EB_D, EPSB);
        float ee   = eps * (sinA * EDCOEF);     // eps * eps_deriv
        s_p1[ly][lx] = ee * gxr;                //  eps*eps'*phidx (unscaled)
        s_p2[ly][lx] = -ee * gyr;               // -eps*eps'*phidy (unscaled)
        s_e2[ly][lx] = eps * eps;
    }
    __syncthreads();

    // --- stage 2: one output point per thread
    {
        const int ly = ty + 1, lx = tx + 1;  // prod/tempr coords
        const int py = ty + 2, px = tx + 2;  // phi coords

        float u = s_phi[py][px];
        float lapp = (s_phi[py][px+1] + s_phi[py][px-1]
                    + s_phi[py+1][px] + s_phi[py-1][px] - 4.0f * u) * INVDX2;
        float T = s_tmp[ly][lx];
        float lapt = (s_tmp[ly][lx+1] + s_tmp[ly][lx-1]
                    + s_tmp[ly+1][lx] + s_tmp[ly-1][lx] - 4.0f * T) * INVDX2;

        // term1 + term2 = [d/dy prod1 + d/dx prod2]; both raw-diff pairs share
        // the same 1/(2dx)*1/(2dy) scale since dx==dy.
        float tt = ((s_p1[ly+1][lx] - s_p1[ly-1][lx])
                  + (s_p2[ly][lx+1] - s_p2[ly][lx-1])) * C_CROSS;

        float m = APIX * atanf(GAMMA_ * (TEQ_ - T));
        float g = u * (1.0f - u) * (u - 0.5f + m);
        float dphi = DTTAU * (tt + s_e2[ly][lx] * lapp + g);

        int o = base + (y0 + ty) * Wd + (x0 + tx);
        out_phi[o] = u + dphi;
        out_tmp[o] = fmaf(KAPPA_, dphi, fmaf(DTc, lapt, T));
    }
}

extern "C" void kernel_launch(void* const* d_in, const int* in_sizes, int n_in,
                              void* d_out, int out_size)
{
    const float* phi   = (const float*)d_in[0];
    const float* tempr = (const float*)d_in[1];
    float* out = (float*)d_out;
    float* out_phi = out;
    float* out_tmp = out + (size_t)BATCH * Hd * Wd;

    dim3 block(TX, TY);
    dim3 grid(Wd / TX, Hd / TY, BATCH);
    dendrite_kernel<<<grid, block>>>(phi, tempr, out_phi, out_tmp);
}

// round 3
// speedup vs baseline: 2.4407x; 2.4407x over previous
#include <cuda_runtime.h>

// Kobayashi dendrite growth, single timestep, fused + float4-vectorized.
// B=4, H=W=2048, periodic boundaries, fp32.
// Output: [phi_new (B*H*W) | tempr_new (B*H*W)] concatenated.

#define Wd 2048
#define Hd 2048
#define MASK 2047
#define BATCH 4

#define BX 16
#define BY 16
#define VX 4
#define VY 2
#define TILEX 64      // BX*VX
#define TILEY 32      // BY*VY

#define SPW 72        // shared row width in floats (x: -4..67, f4-aligned)
#define PH_ROWS 36    // phi rows: y -2..33
#define Q_ROWS  34    // tempr/prod rows: y -1..32

// Physical constants
#define EPSB    0.01f
#define EB_D    2.0e-4f       // EPSB * DELTA
#define EDCOEF  (-1.2e-3f)    // -EPSB * ANISO * DELTA
#define C6T0    0.3623577545f // cos(6*0.2)
#define S6T0    0.9320390860f // sin(6*0.2)
#define APIX    0.2864788976f // ALPHA/pi
#define GAMMA_  10.0f
#define TEQ_    1.0f
#define DTTAU   (1.0f/3.0f)   // DT/TAU
#define DTc     1.0e-4f
#define KAPPA_  1.8f
#define INVDX2  1111.111111f  // 1/dx^2  (dx=dy=0.03)
#define C_CROSS 277.7777778f  // 1/(2dx) * 1/(2dy)
#define PIO2    1.5707963268f

// anisotropy chain: from raw central differences (unscaled) produce
// p1 = eps*eps'*gx, p2 = -eps*eps'*gy, e2 = eps^2   (all with unscaled grads)
__device__ __forceinline__ void aniso(float gx, float gy,
                                      float& p1, float& p2, float& e2)
{
    float r2 = fmaf(gx, gx, gy * gy);
    float inv = rsqrtf(r2);
    float c = gx * inv, s = gy * inv;
    if (r2 == 0.0f) { c = 1.0f; s = 0.0f; }   // atan2(0,0)=0 convention
    float x2 = c * c;
    float c6 = fmaf(fmaf(fmaf(x2, 32.0f, -48.0f), x2, 18.0f), x2, -1.0f);
    float s6 = (s * c) * fmaf(fmaf(x2, 32.0f, -32.0f), x2, 6.0f);
    float cosA = fmaf(c6, C6T0, s6 * S6T0);
    float sinA = fmaf(s6, C6T0, -c6 * S6T0);
    float eps  = fmaf(cosA, EB_D, EPSB);
    float ee   = eps * (sinA * EDCOEF);
    p1 = ee * gx;
    p2 = -ee * gy;
    e2 = eps * eps;
}

// atan for z >= 0 (arg here is GAMMA*(1-T), T in [0,1)). Minimax deg-11, err ~2e-7.
__device__ __forceinline__ float atan_pos(float z)
{
    float t = fminf(z, __fdividef(1.0f, z));   // z=0 -> fmin(0, inf) = 0
    float x2 = t * t;
    float p = fmaf(x2, -0.0117212f, 0.05265332f);
    p = fmaf(p, x2, -0.11643287f);
    p = fmaf(p, x2,  0.19354346f);
    p = fmaf(p, x2, -0.33262347f);
    p = fmaf(p, x2,  0.99997726f);
    p *= t;
    return (z > 1.0f) ? (PIO2 - p) : p;
}

__global__ __launch_bounds__(BX*BY, 4)
void dendrite_kernel(const float* __restrict__ phi,
                     const float* __restrict__ tempr,
                     float* __restrict__ out_phi,
                     float* __restrict__ out_tmp)
{
    __shared__ alignas(16) float s_phi[PH_ROWS * SPW];
    __shared__ alignas(16) float s_tmp[Q_ROWS * SPW];
    __shared__ alignas(16) float s_p1 [Q_ROWS * SPW];
    __shared__ alignas(16) float s_p2 [Q_ROWS * SPW];
    __shared__ alignas(16) float s_e2 [Q_ROWS * SPW];

    const int tx  = threadIdx.x;
    const int ty  = threadIdx.y;
    const int tid = ty * BX + tx;
    const int x0  = blockIdx.x * TILEX;
    const int y0  = blockIdx.y * TILEY;
    const int base = (int)blockIdx.z * (Hd * Wd);

    // ---- load phi: 36 rows x 18 float4 (x0-4 .. x0+67), periodic wrap
    for (int i = tid; i < PH_ROWS * 18; i += BX * BY) {
        int r = i / 18, c = i - r * 18;
        int gy = (y0 + r - 2) & MASK;
        int gx = (x0 + c * 4 - 4) & MASK;
        *(float4*)&s_phi[r * SPW + c * 4] =
            *(const float4*)&phi[base + gy * Wd + gx];
    }
    // ---- load tempr: 34 rows x 18 float4
    for (int i = tid; i < Q_ROWS * 18; i += BX * BY) {
        int r = i / 18, c = i - r * 18;
        int gy = (y0 + r - 1) & MASK;
        int gx = (x0 + c * 4 - 4) & MASK;
        *(float4*)&s_tmp[r * SPW + c * 4] =
            *(const float4*)&tempr[base + gy * Wd + gx];
    }
    __syncthreads();

    // ---- stage 1: p1, p2, e2 over 34 rows x 18 f4-groups (x -4..67; only
    //      x in [-1,64] is consumed downstream, boundary garbage never read)
    for (int i = tid; i < Q_ROWS * 18; i += BX * BY) {
        int r = i / 18, c4 = (i - r * 18) * 4;
        int pb = (r + 1) * SPW + c4;
        float4 pc = *(const float4*)&s_phi[pb];
        float  pl = s_phi[pb - 1];            // c4=0: in-array garbage, unused
        float  pr = s_phi[pb + 4];            // c4=68: in-array garbage, unused
        float4 pu = *(const float4*)&s_phi[r * SPW + c4];
        float4 pd = *(const float4*)&s_phi[(r + 2) * SPW + c4];
        float4 q1, q2, qe;
        aniso(pc.y - pl,   pd.x - pu.x, q1.x, q2.x, qe.x);
        aniso(pc.z - pc.x, pd.y - pu.y, q1.y, q2.y, qe.y);
        aniso(pc.w - pc.y, pd.z - pu.z, q1.z, q2.z, qe.z);
        aniso(pr - pc.z,   pd.w - pu.w, q1.w, q2.w, qe.w);
        *(float4*)&s_p1[r * SPW + c4] = q1;
        *(float4*)&s_p2[r * SPW + c4] = q2;
        *(float4*)&s_e2[r * SPW + c4] = qe;
    }
    __syncthreads();

    // ---- stage 2: each thread computes a 4(x) x 2(y) micro-tile
    const int x  = tx * VX;        // 0..60
    const int cx = x + 4;          // shared col of component .x
    const int yb = ty * VY;        // 0..30
    const int obase = base + (y0 + yb) * Wd + (x0 + x);

    #pragma unroll
    for (int j = 0; j < VY; j++) {
        const int y = yb + j;
        const int prow = (y + 2) * SPW + cx;   // phi center row
        const int qrow = (y + 1) * SPW + cx;   // tempr/prod center row

        float4 u  = *(const float4*)&s_phi[prow];
        float4 pu = *(const float4*)&s_phi[prow - SPW];
        float4 pd = *(const float4*)&s_phi[prow + SPW];
        float  pl = s_phi[prow - 1], pr = s_phi[prow + 4];

        float4 T  = *(const float4*)&s_tmp[qrow];
        float4 tu = *(const float4*)&s_tmp[qrow - SPW];
        float4 td = *(const float4*)&s_tmp[qrow + SPW];
        float  tl = s_tmp[qrow - 1], tr = s_tmp[qrow + 4];

        float4 au = *(const float4*)&s_p1[qrow - SPW];
        float4 ad = *(const float4*)&s_p1[qrow + SPW];
        float4 bc = *(const float4*)&s_p2[qrow];
        float  bl = s_p2[qrow - 1], br = s_p2[qrow + 4];
        float4 e2 = *(const float4*)&s_e2[qrow];

        float4 lapp, lapt, tt;
        lapp.x = fmaf(-4.0f, u.x, pu.x + pd.x + pl  + u.y) * INVDX2;
        lapp.y = fmaf(-4.0f, u.y, pu.y + pd.y + u.x + u.z) * INVDX2;
        lapp.z = fmaf(-4.0f, u.z, pu.z + pd.z + u.y + u.w) * INVDX2;
        lapp.w = fmaf(-4.0f, u.w, pu.w + pd.w + u.z + pr ) * INVDX2;

        lapt.x = fmaf(-4.0f, T.x, tu.x + td.x + tl  + T.y) * INVDX2;
        lapt.y = fmaf(-4.0f, T.y, tu.y + td.y + T.x + T.z) * INVDX2;
        lapt.z = fmaf(-4.0f, T.z, tu.z + td.z + T.y + T.w) * INVDX2;
        lapt.w = fmaf(-4.0f, T.w, tu.w + td.w + T.z + pr*0.0f + tr) * INVDX2;

        tt.x = ((ad.x - au.x) + (bc.y - bl  )) * C_CROSS;
        tt.y = ((ad.y - au.y) + (bc.z - bc.x)) * C_CROSS;
        tt.z = ((ad.z - au.z) + (bc.w - bc.y)) * C_CROSS;
        tt.w = ((ad.w - au.w) + (br   - bc.z)) * C_CROSS;

        float4 op, ot;
        {
            float m, g, dphi;
            m = APIX * atan_pos(GAMMA_ * (TEQ_ - T.x));
            g = u.x * (1.0f - u.x) * (u.x - 0.5f + m);
            dphi = DTTAU * (tt.x + e2.x * lapp.x + g);
            op.x = u.x + dphi;  ot.x = fmaf(KAPPA_, dphi, fmaf(DTc, lapt.x, T.x));
            m = APIX * atan_pos(GAMMA_ * (TEQ_ - T.y));
            g = u.y * (1.0f - u.y) * (u.y - 0.5f + m);
            dphi = DTTAU * (tt.y + e2.y * lapp.y + g);
            op.y = u.y + dphi;  ot.y = fmaf(KAPPA_, dphi, fmaf(DTc, lapt.y, T.y));
            m = APIX * atan_pos(GAMMA_ * (TEQ_ - T.z));
            g = u.z * (1.0f - u.z) * (u.z - 0.5f + m);
            dphi = DTTAU * (tt.z + e2.z * lapp.z + g);
            op.z = u.z + dphi;  ot.z = fmaf(KAPPA_, dphi, fmaf(DTc, lapt.z, T.z));
            m = APIX * atan_pos(GAMMA_ * (TEQ_ - T.w));
            g = u.w * (1.0f - u.w) * (u.w - 0.5f + m);
            dphi = DTTAU * (tt.w + e2.w * lapp.w + g);
            op.w = u.w + dphi;  ot.w = fmaf(KAPPA_, dphi, fmaf(DTc, lapt.w, T.w));
        }
        *(float4*)&out_phi[obase + j * Wd] = op;
        *(float4*)&out_tmp[obase + j * Wd] = ot;
    }
}

extern "C" void kernel_launch(void* const* d_in, const int* in_sizes, int n_in,
                              void* d_out, int out_size)
{
    const float* phi   = (const float*)d_in[0];
    const float* tempr = (const float*)d_in[1];
    float* out = (float*)d_out;
    float* out_phi = out;
    float* out_tmp = out + (size_t)BATCH * Hd * Wd;

    dim3 block(BX, BY);
    dim3 grid(Wd / TILEX, Hd / TILEY, BATCH);
    dendrite_kernel<<<grid, block>>>(phi, tempr, out_phi, out_tmp);
}

// round 4
// speedup vs baseline: 3.3457x; 1.3708x over previous
#include <cuda_runtime.h>

// Kobayashi dendrite growth, single timestep.
// Register-resident y-sweep, warp-shuffle x-exchange, zero shared memory.
// B=4, H=W=2048, periodic, fp32. Output: [phi_new | tempr_new].

#define Wd 2048
#define Hd 2048
#define MASK 2047
#define BATCH 4
#define VY 16          // rows per warp strip
#define NWARP 4        // warps per block

// Physical constants
#define EPSB    0.01f
#define EB_D    2.0e-4f       // EPSB * DELTA
#define EDCOEF  (-1.2e-3f)    // -EPSB * ANISO * DELTA
#define C6T0    0.3623577545f // cos(6*0.2)
#define S6T0    0.9320390860f // sin(6*0.2)
#define APIX    0.2864788976f // ALPHA/pi
#define GAMMA_  10.0f
#define TEQ_    1.0f
#define DTTAU   (1.0f/3.0f)   // DT/TAU
#define DTc     1.0e-4f
#define KAPPA_  1.8f
#define INVDX2  1111.111111f  // 1/dx^2 (dx=dy=0.03)
#define C_CROSS 277.7777778f  // 1/(2dx) * 1/(2dy)
#define PIO2    1.5707963268f

#define FULLM 0xffffffffu

// From raw (unscaled) central differences produce
// p1 = eps*eps'*gx, p2 = -eps*eps'*gy, e2 = eps^2.
__device__ __forceinline__ void aniso(float gx, float gy,
                                      float& p1, float& p2, float& e2)
{
    float r2 = fmaf(gx, gx, gy * gy);
    float inv = rsqrtf(r2);
    float c = gx * inv, s = gy * inv;
    if (r2 == 0.0f) { c = 1.0f; s = 0.0f; }   // atan2(0,0)=0 convention
    float x2 = c * c;
    float c6 = fmaf(fmaf(fmaf(x2, 32.0f, -48.0f), x2, 18.0f), x2, -1.0f);
    float s6 = (s * c) * fmaf(fmaf(x2, 32.0f, -32.0f), x2, 6.0f);
    float cosA = fmaf(c6, C6T0, s6 * S6T0);
    float sinA = fmaf(s6, C6T0, -c6 * S6T0);
    float eps  = fmaf(cosA, EB_D, EPSB);
    float ee   = eps * (sinA * EDCOEF);
    p1 = ee * gx;
    p2 = -ee * gy;
    e2 = eps * eps;
}

// atan for z >= 0 (arg is GAMMA*(1-T), T in [0,1)). Minimax, err ~2e-7.
__device__ __forceinline__ float atan_pos(float z)
{
    float t = fminf(z, __fdividef(1.0f, z));
    float x2 = t * t;
    float p = fmaf(x2, -0.0117212f, 0.05265332f);
    p = fmaf(p, x2, -0.11643287f);
    p = fmaf(p, x2,  0.19354346f);
    p = fmaf(p, x2, -0.33262347f);
    p = fmaf(p, x2,  0.99997726f);
    p *= t;
    return (z > 1.0f) ? (PIO2 - p) : p;
}

__global__ __launch_bounds__(NWARP * 32, 5)
void dendrite_kernel(const float* __restrict__ phi,
                     const float* __restrict__ tempr,
                     float* __restrict__ out_phi,
                     float* __restrict__ out_tmp)
{
    const int lane = threadIdx.x & 31;
    const int warp = threadIdx.x >> 5;
    const int x0 = blockIdx.x * 128;
    const int y0 = (blockIdx.y * NWARP + warp) * VY;
    const int base = (int)blockIdx.z * (Hd * Wd);
    const float* Pp = phi + base;
    const float* Tp = tempr + base;

    const int xc = x0 + lane * 4;
    const bool eL = (lane == 0);
    const bool eR = (lane == 31);
    const bool edge = eL || eR;
    // float2 phi halo column pair: lane0 -> (x0-2, x0-1); lane31 -> (x0+128, x0+129)
    const int xh2 = eL ? ((x0 - 2) & MASK) : ((x0 + 128) & MASK);
    // scalar tempr halo: lane0 -> x0-1 ; lane31 -> x0+128
    const int xh1 = eL ? ((x0 - 1) & MASK) : ((x0 + 128) & MASK);

    auto ldP4 = [&](int y) -> float4 {
        return *(const float4*)(Pp + ((y & MASK) << 11) + xc);
    };
    auto ldT4 = [&](int y) -> float4 {
        return *(const float4*)(Tp + ((y & MASK) << 11) + xc);
    };
    auto ldPH = [&](int y) -> float2 {
        float2 h = make_float2(1.0f, 1.0f);
        if (edge) h = *(const float2*)(Pp + ((y & MASK) << 11) + xh2);
        return h;
    };
    auto ldTH = [&](int y) -> float {
        float s = 0.0f;
        if (edge) s = Tp[((y & MASK) << 11) + xh1];
        return s;
    };

    // aniso over one row: pm/pc/pp = phi rows y-1,y,y+1; hm/hc/hp their halos.
    // Outputs q1,q2,e2v for own 4 columns + h2 = p2 at the halo column
    // (x0-1 on lane0, x0+128 on lane31; garbage elsewhere, never read).
    auto aniso_row = [&](const float4& pm, const float4& pc, const float4& pp,
                         const float2& hm, const float2& hc, const float2& hp,
                         float4& q1, float4& q2, float4& e2v, float& h2)
    {
        float pl = __shfl_up_sync(FULLM, pc.w, 1);
        if (eL) pl = hc.y;
        float pr = __shfl_down_sync(FULLM, pc.x, 1);
        if (eR) pr = hc.x;
        aniso(pc.y - pl,   pp.x - pm.x, q1.x, q2.x, e2v.x);
        aniso(pc.z - pc.x, pp.y - pm.y, q1.y, q2.y, e2v.y);
        aniso(pc.w - pc.y, pp.z - pm.z, q1.z, q2.z, e2v.z);
        aniso(pr - pc.z,   pp.w - pm.w, q1.w, q2.w, e2v.w);
        float gxh = eL ? (pc.x - hc.x) : (hc.y - pc.w);
        float gyh = eL ? (hp.y - hm.y) : (hp.x - hm.x);
        float d1, d3;
        aniso(gxh, gyh, d1, h2, d3);
        (void)d1; (void)d3;
    };

    // ---- prologue: windows for rows y0-1 .. y0+1
    float4 pZ = ldP4(y0 - 2);
    float4 pA = ldP4(y0 - 1);  float2 hA = ldPH(y0 - 1);
    float4 pB = ldP4(y0);      float2 hB = ldPH(y0);
    float4 pC = ldP4(y0 + 1);  float2 hC = ldPH(y0 + 1);
    float4 tA = ldT4(y0 - 1);
    float4 tB = ldT4(y0);      float  sB = ldTH(y0);

    float4 q1A, q2A, e2A; float h2A;   // row y0-1 (only q1A consumed)
    aniso_row(pZ, pA, pB, hA, hA, hA, q1A, q2A, e2A, h2A);
    float4 q1B, q2B, e2B; float h2B;   // row y0
    aniso_row(pA, pB, pC, hA, hB, hC, q1B, q2B, e2B, h2B);

    #pragma unroll 4
    for (int r = y0; r < y0 + VY; ++r) {
        float4 pD = ldP4(r + 2);  float2 hD = ldPH(r + 2);
        float4 tC = ldT4(r + 1);  float  sC = ldTH(r + 1);

        float4 q1C, q2C, e2C; float h2C;   // row r+1
        aniso_row(pB, pC, pD, hB, hC, hD, q1C, q2C, e2C, h2C);

        // ---- output at row r
        float pl = __shfl_up_sync(FULLM, pB.w, 1);   if (eL) pl = hB.y;
        float pr = __shfl_down_sync(FULLM, pB.x, 1); if (eR) pr = hB.x;
        float tl = __shfl_up_sync(FULLM, tB.w, 1);   if (eL) tl = sB;
        float tr = __shfl_down_sync(FULLM, tB.x, 1); if (eR) tr = sB;
        float bl = __shfl_up_sync(FULLM, q2B.w, 1);  if (eL) bl = h2B;
        float br = __shfl_down_sync(FULLM, q2B.x, 1); if (eR) br = h2B;

        float4 lapp, lapt, tt;
        lapp.x = fmaf(-4.0f, pB.x, pA.x + pC.x + pl   + pB.y) * INVDX2;
        lapp.y = fmaf(-4.0f, pB.y, pA.y + pC.y + pB.x + pB.z) * INVDX2;
        lapp.z = fmaf(-4.0f, pB.z, pA.z + pC.z + pB.y + pB.w) * INVDX2;
        lapp.w = fmaf(-4.0f, pB.w, pA.w + pC.w + pB.z + pr  ) * INVDX2;

        lapt.x = fmaf(-4.0f, tB.x, tA.x + tC.x + tl   + tB.y) * INVDX2;
        lapt.y = fmaf(-4.0f, tB.y, tA.y + tC.y + tB.x + tB.z) * INVDX2;
        lapt.z = fmaf(-4.0f, tB.z, tA.z + tC.z + tB.y + tB.w) * INVDX2;
        lapt.w = fmaf(-4.0f, tB.w, tA.w + tC.w + tB.z + tr  ) * INVDX2;

        tt.x = ((q1C.x - q1A.x) + (q2B.y - bl   )) * C_CROSS;
        tt.y = ((q1C.y - q1A.y) + (q2B.z - q2B.x)) * C_CROSS;
        tt.z = ((q1C.z - q1A.z) + (q2B.w - q2B.y)) * C_CROSS;
        tt.w = ((q1C.w - q1A.w) + (br    - q2B.z)) * C_CROSS;

        float4 op, ot;
        {
            float m, g, dphi;
            m = APIX * atan_pos(GAMMA_ * (TEQ_ - tB.x));
            g = pB.x * (1.0f - pB.x) * (pB.x - 0.5f + m);
            dphi = DTTAU * (tt.x + e2B.x * lapp.x + g);
            op.x = pB.x + dphi; ot.x = fmaf(KAPPA_, dphi, fmaf(DTc, lapt.x, tB.x));

            m = APIX * atan_pos(GAMMA_ * (TEQ_ - tB.y));
            g = pB.y * (1.0f - pB.y) * (pB.y - 0.5f + m);
            dphi = DTTAU * (tt.y + e2B.y * lapp.y + g);
            op.y = pB.y + dphi; ot.y = fmaf(KAPPA_, dphi, fmaf(DTc, lapt.y, tB.y));

            m = APIX * atan_pos(GAMMA_ * (TEQ_ - tB.z));
            g = pB.z * (1.0f - pB.z) * (pB.z - 0.5f + m);
            dphi = DTTAU * (tt.z + e2B.z * lapp.z + g);
            op.z = pB.z + dphi; ot.z = fmaf(KAPPA_, dphi, fmaf(DTc, lapt.z, tB.z));

            m = APIX * atan_pos(GAMMA_ * (TEQ_ - tB.w));
            g = pB.w * (1.0f - pB.w) * (pB.w - 0.5f + m);
            dphi = DTTAU * (tt.w + e2B.w * lapp.w + g);
            op.w = pB.w + dphi; ot.w = fmaf(KAPPA_, dphi, fmaf(DTc, lapt.w, tB.w));
        }
        const int o = base + (r << 11) + xc;
        *(float4*)(out_phi + o) = op;
        *(float4*)(out_tmp + o) = ot;

        // ---- shift windows
        pA = pB; pB = pC; pC = pD;
        hB = hC; hC = hD;
        tA = tB; tB = tC; sB = sC;
        q1A = q1B; q1B = q1C;
        q2B = q2C; h2B = h2C; e2B = e2C;
    }
}

extern "C" void kernel_launch(void* const* d_in, const int* in_sizes, int n_in,
                              void* d_out, int out_size)
{
    const float* phi   = (const float*)d_in[0];
    const float* tempr = (const float*)d_in[1];
    float* out = (float*)d_out;
    float* out_phi = out;
    float* out_tmp = out + (size_t)BATCH * Hd * Wd;

    dim3 block(NWARP * 32);
    dim3 grid(Wd / 128, Hd / VY / NWARP, BATCH);
    dendrite_kernel<<<grid, block>>>(phi, tempr, out_phi, out_tmp);
}